// round 9
// baseline (speedup 1.0000x reference)
#include <cuda_runtime.h>
#include <math.h>

#define BATCH 8
#define NCLS 3
#define H 384
#define W 384
#define HW (H*W)
#define NBC 24
#define JT 8
#define NWARP 12   // 384/32
#define NWORD 12   // H/32 mask words per column
#define R 8        // rows per k2 block
#define RG (H/R)   // 48 row-groups
#define P 32       // pad columns each side (tail guard)
#define RU 6       // branch-free unrolled EDT radius
#define SENT2 1046529.0f   // 1023^2

// Scratch (device globals, fully overwritten each launch)
// layout: [b][c][word][j]
__device__ unsigned g_mask[BATCH*3*NWORD*W];
__device__ int      g_pn  [BATCH*3*NWORD*W];   // low16 = prev row (s16), high16 = next row (s16)
__device__ float g_psum_bg[NBC*RG];
__device__ float g_psum_fg[NBC*RG];
__device__ float g_pmax_bg[NBC*RG];
__device__ float g_pmax_fg[NBC*RG];

// ---------------------------------------------------------------------------
// k1: build per-column class bitmasks via ballot (thread = row, 8-col tile)
// and per (col,class,word) nearest-set-row below/above (prev/next, s16 pair).
// ---------------------------------------------------------------------------
__global__ void __launch_bounds__(384) k1_masks(const int* __restrict__ targets) {
    __shared__ unsigned sm[NWORD][24];   // [word][jj*3+c]
    const int i = threadIdx.x;           // row
    const int lane = i & 31, w = i >> 5;
    const int b = blockIdx.y;
    const int j0 = blockIdx.x * JT;

    const int4* tp = (const int4*)(targets + b*HW + i*W + j0);
    int4 ta = tp[0], tb = tp[1];         // two independent LDG.128
    int t[8] = {ta.x, ta.y, ta.z, ta.w, tb.x, tb.y, tb.z, tb.w};

    unsigned bal[24];
    #pragma unroll
    for (int jj = 0; jj < 8; jj++) {
        unsigned b0 = __ballot_sync(0xffffffffu, t[jj] == 0);
        unsigned b1 = __ballot_sync(0xffffffffu, t[jj] == 1);
        bal[jj*3+0] = b0;
        bal[jj*3+1] = b1;
        bal[jj*3+2] = ~(b0 | b1);
    }
    if (lane == 0) {
        #pragma unroll
        for (int c = 0; c < 3; c++) {
            uint4* gm = (uint4*)&g_mask[((b*3 + c)*NWORD + w)*W + j0];
            gm[0] = make_uint4(bal[0*3+c], bal[1*3+c], bal[2*3+c], bal[3*3+c]);
            gm[1] = make_uint4(bal[4*3+c], bal[5*3+c], bal[6*3+c], bal[7*3+c]);
        }
        uint4* sp = (uint4*)sm[w];
        #pragma unroll
        for (int q = 0; q < 6; q++)
            sp[q] = make_uint4(bal[q*4+0], bal[q*4+1], bal[q*4+2], bal[q*4+3]);
    }
    __syncthreads();

    if (threadIdx.x < 288) {   // one thread per (c, jj, word)
        const int tt = threadIdx.x;
        const int c = tt / 96, r96 = tt % 96;
        const int jj = r96 / NWORD, w2 = r96 % NWORD;
        const int s = jj*3 + c;
        int prev = -2000;
        for (int ww = w2 - 1; ww >= 0; --ww) {
            unsigned m = sm[ww][s];
            if (m) { prev = ww*32 + 31 - __clz(m); break; }
        }
        int next = 3000;
        for (int ww = w2 + 1; ww < NWORD; ++ww) {
            unsigned m = sm[ww][s];
            if (m) { next = ww*32 + __ffs(m) - 1; break; }
        }
        g_pn[((b*3 + c)*NWORD + w2)*W + j0 + jj] =
            (int)(((unsigned)(prev & 0xffff)) | ((unsigned)next << 16));
    }
}

// ---------------------------------------------------------------------------
// k2: transposed-tile fused kernel. smem layout [class][P+j][8 rows] so one
// thread updates 8 rows of a class with 2x LDS.128 per side. Branch-free
// unrolled EDT r=1..RU (monotone extra updates are exact no-ops), rare
// pad-guarded tail + bounds-checked cold path. MUFU-minimized epilogue.
// ---------------------------------------------------------------------------
__global__ void __launch_bounds__(384) k2_fused(const float* __restrict__ logits) {
    __shared__ float sh[3][W + 2*P][R];   // [class][P + j][row]
    __shared__ float red[NWARP][12];
    const int j = threadIdx.x;
    const int rg = blockIdx.x, b = blockIdx.y;
    const int row0 = rg * R;
    const int w = row0 >> 5;          // single mask word for all 8 rows
    const int lane = j & 31, wid = j >> 5;

    // sentinel pads: columns [0,P) and [W+P, W+2P)
    if (j < 2*P) {
        const int q = (j < P) ? j : (W + j);
        const float4 sv = make_float4(SENT2, SENT2, SENT2, SENT2);
        #pragma unroll
        for (int c = 0; c < 3; c++) {
            *(float4*)&sh[c][q][0] = sv;
            *(float4*)&sh[c][q][4] = sv;
        }
    }

    const int mbase = ((b*3)*NWORD + w)*W + j;   // class stride = NWORD*W
    float bb[3][R];   // per-class, per-row running best (d^2), init = g^2
    #pragma unroll
    for (int c = 0; c < 3; c++) {
        const unsigned mwc = g_mask[mbase + c*NWORD*W];
        const int pn = g_pn[mbase + c*NWORD*W];
        const int prv = (int)(short)(pn & 0xffff);
        const int nxt = pn >> 16;
        #pragma unroll
        for (int ri = 0; ri < R; ri++) {
            const int row = row0 + ri;
            const int lr = row & 31;
            const unsigned lowmask = 0xffffffffu >> (31 - lr);
            const unsigned himask  = 0xffffffffu << lr;
            unsigned mlo = mwc & lowmask;
            int dfw = mlo ? (lr + __clz(mlo) - 31) : (row - prv);
            unsigned mhi = mwc & himask;
            int dbw = mhi ? (__ffs(mhi) - 1 - lr) : (nxt - row);
            int g = min(min(dfw, dbw), 1023);
            bb[c][ri] = (float)(g * g);
        }
        *(float4*)&sh[c][P + j][0] = make_float4(bb[c][0], bb[c][1], bb[c][2], bb[c][3]);
        *(float4*)&sh[c][P + j][4] = make_float4(bb[c][4], bb[c][5], bb[c][6], bb[c][7]);
    }
    __syncthreads();

    // EDT: branch-free unrolled prefix (exact: extra min-updates are no-ops)
    #pragma unroll
    for (int r = 1; r <= RU; r++) {
        const float rr = (float)(r * r);
        #pragma unroll
        for (int c = 0; c < 3; c++) {
            float4 lo0 = *(const float4*)&sh[c][P + j - r][0];
            float4 lo1 = *(const float4*)&sh[c][P + j - r][4];
            float4 hi0 = *(const float4*)&sh[c][P + j + r][0];
            float4 hi1 = *(const float4*)&sh[c][P + j + r][4];
            bb[c][0] = fminf(bb[c][0], fminf(lo0.x, hi0.x) + rr);
            bb[c][1] = fminf(bb[c][1], fminf(lo0.y, hi0.y) + rr);
            bb[c][2] = fminf(bb[c][2], fminf(lo0.z, hi0.z) + rr);
            bb[c][3] = fminf(bb[c][3], fminf(lo0.w, hi0.w) + rr);
            bb[c][4] = fminf(bb[c][4], fminf(lo1.x, hi1.x) + rr);
            bb[c][5] = fminf(bb[c][5], fminf(lo1.y, hi1.y) + rr);
            bb[c][6] = fminf(bb[c][6], fminf(lo1.z, hi1.z) + rr);
            bb[c][7] = fminf(bb[c][7], fminf(lo1.w, hi1.w) + rr);
        }
    }
    // tail: rare (P[any of 24 g >= RU+2] small). Pad-guarded to r <= P.
    float bm = 0.0f;
    #pragma unroll
    for (int c = 0; c < 3; c++)
        #pragma unroll
        for (int ri = 0; ri < R; ri++) bm = fmaxf(bm, bb[c][ri]);
    {
        int r = RU + 1;
        float rf = (float)(RU + 1);
        while (rf*rf < bm && r <= P) {
            const float rr = rf * rf;
            #pragma unroll
            for (int c = 0; c < 3; c++) {
                float4 lo0 = *(const float4*)&sh[c][P + j - r][0];
                float4 lo1 = *(const float4*)&sh[c][P + j - r][4];
                float4 hi0 = *(const float4*)&sh[c][P + j + r][0];
                float4 hi1 = *(const float4*)&sh[c][P + j + r][4];
                bb[c][0] = fminf(bb[c][0], fminf(lo0.x, hi0.x) + rr);
                bb[c][1] = fminf(bb[c][1], fminf(lo0.y, hi0.y) + rr);
                bb[c][2] = fminf(bb[c][2], fminf(lo0.z, hi0.z) + rr);
                bb[c][3] = fminf(bb[c][3], fminf(lo0.w, hi0.w) + rr);
                bb[c][4] = fminf(bb[c][4], fminf(lo1.x, hi1.x) + rr);
                bb[c][5] = fminf(bb[c][5], fminf(lo1.y, hi1.y) + rr);
                bb[c][6] = fminf(bb[c][6], fminf(lo1.z, hi1.z) + rr);
                bb[c][7] = fminf(bb[c][7], fminf(lo1.w, hi1.w) + rr);
            }
            bm = 0.0f;
            #pragma unroll
            for (int c = 0; c < 3; c++)
                #pragma unroll
                for (int ri = 0; ri < R; ri++) bm = fmaxf(bm, bb[c][ri]);
            r++; rf += 1.0f;
        }
        // cold exact fallback (r > P): bounds-checked scalar walks
        while (rf*rf < bm && r < W) {
            const float rr = rf * rf;
            const int lo = j - r, hi = j + r;
            #pragma unroll
            for (int c = 0; c < 3; c++)
                #pragma unroll
                for (int ri = 0; ri < R; ri++) {
                    float v = bb[c][ri];
                    if (lo >= 0) v = fminf(v, sh[c][P + lo][ri] + rr);
                    if (hi < W)  v = fminf(v, sh[c][P + hi][ri] + rr);
                    bb[c][ri] = v;
                }
            bm = 0.0f;
            #pragma unroll
            for (int c = 0; c < 3; c++)
                #pragma unroll
                for (int ri = 0; ri < R; ri++) bm = fmaxf(bm, bb[c][ri]);
            r++; rf += 1.0f;
        }
    }

    float accs[6] = {0,0,0,0,0,0};      // p*dbg, p*dfg per class
    float accm[6] = {0,0,0,0,0,0};      // max d2 bg, max d2 fg per class

    #pragma unroll
    for (int ri = 0; ri < R; ri++) {
        const int row = row0 + ri;
        const float b0 = bb[0][ri], b1 = bb[1][ri], b2 = bb[2][ri];
        // bg sqrts once; fg sqrts = mins of bg sqrts (sqrt monotone)
        float sb0 = sqrtf(b0), sb1 = sqrtf(b1), sb2 = sqrtf(b2);
        float sf0 = fminf(sb1, sb2);
        float sf1 = fminf(sb0, sb2);
        float sf2 = fminf(sb0, sb1);

        // softmax normalized by class 2: e2 = 1 (identical values, 2 MUFU)
        const float* lp = logits + (b*3)*HW + row*W + j;
        float l2v = lp[2*HW];
        float e0 = __expf(lp[0] - l2v), e1 = __expf(lp[HW] - l2v);
        float inv = __fdividef(1.0f, e0 + e1 + 1.0f);
        float p0 = e0*inv, p1 = e1*inv, p2 = inv;

        accs[0] += p0 * sb0;
        accs[1] += p1 * sb1;
        accs[2] += p2 * sb2;
        accs[3] += p0 * sf0;
        accs[4] += p1 * sf1;
        accs[5] += p2 * sf2;
        accm[0] = fmaxf(accm[0], b0);
        accm[1] = fmaxf(accm[1], b1);
        accm[2] = fmaxf(accm[2], b2);
        accm[3] = fmaxf(accm[3], fminf(b1, b2));
        accm[4] = fmaxf(accm[4], fminf(b0, b2));
        accm[5] = fmaxf(accm[5], fminf(b0, b1));
    }

    // warp reduce: 6 sums via shuffles, 6 maxes via redux on positive bits
    #pragma unroll
    for (int off = 16; off; off >>= 1) {
        #pragma unroll
        for (int s = 0; s < 6; s++) accs[s] += __shfl_xor_sync(0xffffffffu, accs[s], off);
    }
    #pragma unroll
    for (int s = 0; s < 6; s++)
        accm[s] = __uint_as_float(__reduce_max_sync(0xffffffffu, __float_as_uint(accm[s])));

    if (lane == 0) {
        #pragma unroll
        for (int s = 0; s < 6; s++) { red[wid][s] = accs[s]; red[wid][6+s] = accm[s]; }
    }
    __syncthreads();
    if (threadIdx.x < 12) {
        int s = threadIdx.x;
        float acc = red[0][s];
        #pragma unroll
        for (int ww = 1; ww < NWARP; ww++)
            acc = (s < 6) ? (acc + red[ww][s]) : fmaxf(acc, red[ww][s]);
        int c = s % 3;
        int idx = (b*3 + c) * RG + rg;
        int grp = s / 3;
        if      (grp == 0) g_psum_bg[idx] = acc;
        else if (grp == 1) g_psum_fg[idx] = acc;
        else if (grp == 2) g_pmax_bg[idx] = sqrtf(acc);   // sqrt(max d2) == max d
        else               g_pmax_fg[idx] = sqrtf(acc);
    }
}

// ---------------------------------------------------------------------------
// k3: final reduce. Warp per (b,c) map; gate = (Mbg < 600) <=> mask nonempty.
// ---------------------------------------------------------------------------
__global__ void k3_final(float* out) {
    const int lane = threadIdx.x & 31, bc = threadIdx.x >> 5;   // 24 warps
    double sbg = 0.0, sfg = 0.0;
    float mbg = 0.0f, mfg = 0.0f;
    for (int r = lane; r < RG; r += 32) {
        sbg += (double)g_psum_bg[bc*RG + r];
        sfg += (double)g_psum_fg[bc*RG + r];
        mbg = fmaxf(mbg, g_pmax_bg[bc*RG + r]);
        mfg = fmaxf(mfg, g_pmax_fg[bc*RG + r]);
    }
    #pragma unroll
    for (int off = 16; off; off >>= 1) {
        sbg += __shfl_xor_sync(0xffffffffu, sbg, off);
        sfg += __shfl_xor_sync(0xffffffffu, sfg, off);
        mbg = fmaxf(mbg, __shfl_xor_sync(0xffffffffu, mbg, off));
        mfg = fmaxf(mfg, __shfl_xor_sync(0xffffffffu, mfg, off));
    }
    __shared__ double cs[24];
    if (lane == 0) {
        double contrib = 0.0;
        if (mbg < 600.0f) {   // mask nonempty (empty-map sentinel d >= 1023)
            contrib = sbg / (double)fmaxf(mbg, 1e-12f)
                    - sfg / (double)fmaxf(mfg, 1e-12f);
        }
        cs[bc] = contrib;
    }
    __syncthreads();
    if (threadIdx.x == 0) {
        double s = 0.0;
        #pragma unroll
        for (int k = 0; k < 24; k++) s += cs[k];
        out[0] = (float)(s / (24.0 * (double)HW));
    }
}

extern "C" void kernel_launch(void* const* d_in, const int* in_sizes, int n_in,
                              void* d_out, int out_size) {
    const float* logits  = (const float*)d_in[0];
    const int*   targets = (const int*)d_in[1];

    dim3 g1(W / JT, BATCH);
    k1_masks<<<g1, H>>>(targets);
    dim3 g2(RG, BATCH);
    k2_fused<<<g2, W>>>(logits);
    k3_final<<<1, 24 * 32>>>((float*)d_out);
}

// round 10
// speedup vs baseline: 1.3303x; 1.3303x over previous
#include <cuda_runtime.h>
#include <math.h>

#define BATCH 8
#define NCLS 3
#define H 384
#define W 384
#define HW (H*W)
#define NBC 24
#define JT 8
#define NWARP 12   // 384/32
#define NWORD 12   // H/32 mask words per column
#define R 4        // rows per k2 block
#define RG (H/R)   // 96 row-groups
#define P 32       // fast-path EDT pad/radius
#define SENT2 1046529.0f   // 1023^2

// Scratch (device globals, fully overwritten each launch)
// layout: [b][c][word][j]
__device__ unsigned g_mask[BATCH*3*NWORD*W];
__device__ int      g_pn  [BATCH*3*NWORD*W];   // low16 = prev row (s16), high16 = next row (s16)
__device__ float g_psum_bg[NBC*RG];
__device__ float g_psum_fg[NBC*RG];
__device__ float g_pmax_bg[NBC*RG];
__device__ float g_pmax_fg[NBC*RG];

// ---------------------------------------------------------------------------
// k1: build per-column class bitmasks via ballot (thread = row, 8-col tile)
// and per (col,class,word) nearest-set-row below/above (prev/next, s16 pair).
// ---------------------------------------------------------------------------
__global__ void __launch_bounds__(384) k1_masks(const int* __restrict__ targets) {
    __shared__ unsigned sm[NWORD][24];   // [word][jj*3+c]
    const int i = threadIdx.x;           // row
    const int lane = i & 31, w = i >> 5;
    const int b = blockIdx.y;
    const int j0 = blockIdx.x * JT;

    const int4* tp = (const int4*)(targets + b*HW + i*W + j0);
    int4 ta = tp[0], tb = tp[1];         // two independent LDG.128
    int t[8] = {ta.x, ta.y, ta.z, ta.w, tb.x, tb.y, tb.z, tb.w};

    unsigned bal[24];
    #pragma unroll
    for (int jj = 0; jj < 8; jj++) {
        unsigned b0 = __ballot_sync(0xffffffffu, t[jj] == 0);
        unsigned b1 = __ballot_sync(0xffffffffu, t[jj] == 1);
        bal[jj*3+0] = b0;
        bal[jj*3+1] = b1;
        bal[jj*3+2] = ~(b0 | b1);
    }
    if (lane == 0) {
        #pragma unroll
        for (int c = 0; c < 3; c++) {
            uint4* gm = (uint4*)&g_mask[((b*3 + c)*NWORD + w)*W + j0];
            gm[0] = make_uint4(bal[0*3+c], bal[1*3+c], bal[2*3+c], bal[3*3+c]);
            gm[1] = make_uint4(bal[4*3+c], bal[5*3+c], bal[6*3+c], bal[7*3+c]);
        }
        uint4* sp = (uint4*)sm[w];
        #pragma unroll
        for (int q = 0; q < 6; q++)
            sp[q] = make_uint4(bal[q*4+0], bal[q*4+1], bal[q*4+2], bal[q*4+3]);
    }
    __syncthreads();

    if (threadIdx.x < 288) {   // one thread per (c, jj, word)
        const int tt = threadIdx.x;
        const int c = tt / 96, r96 = tt % 96;
        const int jj = r96 / NWORD, w2 = r96 % NWORD;
        const int s = jj*3 + c;
        int prev = -2000;
        for (int ww = w2 - 1; ww >= 0; --ww) {
            unsigned m = sm[ww][s];
            if (m) { prev = ww*32 + 31 - __clz(m); break; }
        }
        int next = 3000;
        for (int ww = w2 + 1; ww < NWORD; ++ww) {
            unsigned m = sm[ww][s];
            if (m) { next = ww*32 + __ffs(m) - 1; break; }
        }
        g_pn[((b*3 + c)*NWORD + w2)*W + j0 + jj] =
            (int)(((unsigned)(prev & 0xffff)) | ((unsigned)next << 16));
    }
}

// ---------------------------------------------------------------------------
// k2: single-barrier fused kernel (round-7 structure, R=4 for wave shape).
// Phase 1: derive all 12 g^2 (3 classes x 4 rows sharing one mask word) into
// padded row-major smem. One __syncthreads. Phase 2: per-row EDT with
// per-pixel exit, 2 radii per loop trip (extra updates are monotone no-ops),
// sentinel pads to r <= P, bounds-checked cold fallback. MUFU-minimized
// epilogue, register accumulators, one block reduction.
// ---------------------------------------------------------------------------
__global__ void __launch_bounds__(384) k2_fused(const float* __restrict__ logits) {
    __shared__ float sh[3][R][W + 2*P];
    __shared__ float red[NWARP][12];
    const int j = threadIdx.x;
    const int rg = blockIdx.x, b = blockIdx.y;
    const int row0 = rg * R;
    const int w = row0 >> 5;          // rows of this block share one mask word
    const int lane = j & 31, wid = j >> 5;

    // sentinel pads
    if (j < 2*P) {
        const int side = (j < P) ? j : (W + j);
        #pragma unroll
        for (int c = 0; c < 3; c++)
            #pragma unroll
            for (int ri = 0; ri < R; ri++)
                sh[c][ri][side] = SENT2;
    }

    const int mbase = ((b*3)*NWORD + w)*W + j;   // class stride = NWORD*W
    unsigned mw[3];
    int prv[3], nxt[3];
    #pragma unroll
    for (int c = 0; c < 3; c++) {
        mw[c] = g_mask[mbase + c*NWORD*W];
        int pn = g_pn[mbase + c*NWORD*W];
        prv[c] = (int)(short)(pn & 0xffff);
        nxt[c] = pn >> 16;
    }

    // phase 1: all column distances -> smem
    #pragma unroll
    for (int ri = 0; ri < R; ri++) {
        const int row = row0 + ri;
        const int lr = row & 31;                         // uniform
        const unsigned lowmask = 0xffffffffu >> (31 - lr);
        const unsigned himask  = 0xffffffffu << lr;
        #pragma unroll
        for (int c = 0; c < 3; c++) {
            unsigned mlo = mw[c] & lowmask;
            int dfw = mlo ? (lr + __clz(mlo) - 31) : (row - prv[c]);
            unsigned mhi = mw[c] & himask;
            int dbw = mhi ? (__ffs(mhi) - 1 - lr) : (nxt[c] - row);
            int g = min(min(dfw, dbw), 1023);
            sh[c][ri][P + j] = (float)(g * g);
        }
    }
    __syncthreads();   // the only block barrier before the reduction

    float accs[6] = {0,0,0,0,0,0};      // p*dbg, p*dfg per class
    float accm[6] = {0,0,0,0,0,0};      // max d2 bg, max d2 fg per class

    #pragma unroll
    for (int ri = 0; ri < R; ri++) {
        const int row = row0 + ri;
        const float* s0 = &sh[0][ri][P];
        const float* s1 = &sh[1][ri][P];
        const float* s2 = &sh[2][ri][P];
        float b0 = s0[j], b1 = s1[j], b2 = s2[j];
        float bestmax = fmaxf(b0, fmaxf(b1, b2));
        float rf = 1.0f;
        int r = 1;
        // fast path: 2 radii per trip (extra updates exact no-ops);
        // pads absorb out-of-range reads up to r+1 <= P
        while (rf*rf < bestmax && r + 1 <= P) {
            const float rr1 = rf*rf;
            const float rr2 = (rf + 1.0f)*(rf + 1.0f);
            b0 = fminf(b0, fminf(s0[j-r],   s0[j+r])   + rr1);
            b1 = fminf(b1, fminf(s1[j-r],   s1[j+r])   + rr1);
            b2 = fminf(b2, fminf(s2[j-r],   s2[j+r])   + rr1);
            b0 = fminf(b0, fminf(s0[j-r-1], s0[j+r+1]) + rr2);
            b1 = fminf(b1, fminf(s1[j-r-1], s1[j+r+1]) + rr2);
            b2 = fminf(b2, fminf(s2[j-r-1], s2[j+r+1]) + rr2);
            bestmax = fmaxf(b0, fmaxf(b1, b2));
            r += 2; rf += 2.0f;
        }
        // exact cold fallback (r > P; only when a class is locally absent)
        while (rf*rf < bestmax && r < W) {
            const float rr = rf*rf;
            const int lo = j - r, hi = j + r;
            if (lo >= 0) {
                b0 = fminf(b0, s0[lo] + rr);
                b1 = fminf(b1, s1[lo] + rr);
                b2 = fminf(b2, s2[lo] + rr);
            }
            if (hi < W) {
                b0 = fminf(b0, s0[hi] + rr);
                b1 = fminf(b1, s1[hi] + rr);
                b2 = fminf(b2, s2[hi] + rr);
            }
            bestmax = fmaxf(b0, fmaxf(b1, b2));
            r++; rf += 1.0f;
        }
        // bg sqrts once; fg sqrts = mins of bg sqrts (sqrt monotone)
        float sb0 = sqrtf(b0), sb1 = sqrtf(b1), sb2 = sqrtf(b2);
        float sf0 = fminf(sb1, sb2);
        float sf1 = fminf(sb0, sb2);
        float sf2 = fminf(sb0, sb1);

        // softmax normalized by class 2: e2 = 1 (identical values, 2 MUFU)
        const float* lp = logits + (b*3)*HW + row*W + j;
        float l2v = lp[2*HW];
        float e0 = __expf(lp[0] - l2v), e1 = __expf(lp[HW] - l2v);
        float inv = __fdividef(1.0f, e0 + e1 + 1.0f);
        float p0 = e0*inv, p1 = e1*inv, p2 = inv;

        accs[0] += p0 * sb0;
        accs[1] += p1 * sb1;
        accs[2] += p2 * sb2;
        accs[3] += p0 * sf0;
        accs[4] += p1 * sf1;
        accs[5] += p2 * sf2;
        accm[0] = fmaxf(accm[0], b0);
        accm[1] = fmaxf(accm[1], b1);
        accm[2] = fmaxf(accm[2], b2);
        accm[3] = fmaxf(accm[3], fminf(b1, b2));
        accm[4] = fmaxf(accm[4], fminf(b0, b2));
        accm[5] = fmaxf(accm[5], fminf(b0, b1));
    }

    // warp reduce: 6 sums via shuffles, 6 maxes via redux on positive bits
    #pragma unroll
    for (int off = 16; off; off >>= 1) {
        #pragma unroll
        for (int s = 0; s < 6; s++) accs[s] += __shfl_xor_sync(0xffffffffu, accs[s], off);
    }
    #pragma unroll
    for (int s = 0; s < 6; s++)
        accm[s] = __uint_as_float(__reduce_max_sync(0xffffffffu, __float_as_uint(accm[s])));

    if (lane == 0) {
        #pragma unroll
        for (int s = 0; s < 6; s++) { red[wid][s] = accs[s]; red[wid][6+s] = accm[s]; }
    }
    __syncthreads();
    if (threadIdx.x < 12) {
        int s = threadIdx.x;
        float acc = red[0][s];
        #pragma unroll
        for (int ww = 1; ww < NWARP; ww++)
            acc = (s < 6) ? (acc + red[ww][s]) : fmaxf(acc, red[ww][s]);
        int c = s % 3;
        int idx = (b*3 + c) * RG + rg;
        int grp = s / 3;
        if      (grp == 0) g_psum_bg[idx] = acc;
        else if (grp == 1) g_psum_fg[idx] = acc;
        else if (grp == 2) g_pmax_bg[idx] = sqrtf(acc);   // sqrt(max d2) == max d
        else               g_pmax_fg[idx] = sqrtf(acc);
    }
}

// ---------------------------------------------------------------------------
// k3: final reduce. Warp per (b,c) map; gate = (Mbg < 600) <=> mask nonempty.
// ---------------------------------------------------------------------------
__global__ void k3_final(float* out) {
    const int lane = threadIdx.x & 31, bc = threadIdx.x >> 5;   // 24 warps
    double sbg = 0.0, sfg = 0.0;
    float mbg = 0.0f, mfg = 0.0f;
    for (int r = lane; r < RG; r += 32) {
        sbg += (double)g_psum_bg[bc*RG + r];
        sfg += (double)g_psum_fg[bc*RG + r];
        mbg = fmaxf(mbg, g_pmax_bg[bc*RG + r]);
        mfg = fmaxf(mfg, g_pmax_fg[bc*RG + r]);
    }
    #pragma unroll
    for (int off = 16; off; off >>= 1) {
        sbg += __shfl_xor_sync(0xffffffffu, sbg, off);
        sfg += __shfl_xor_sync(0xffffffffu, sfg, off);
        mbg = fmaxf(mbg, __shfl_xor_sync(0xffffffffu, mbg, off));
        mfg = fmaxf(mfg, __shfl_xor_sync(0xffffffffu, mfg, off));
    }
    __shared__ double cs[24];
    if (lane == 0) {
        double contrib = 0.0;
        if (mbg < 600.0f) {   // mask nonempty (empty-map sentinel d >= 1023)
            contrib = sbg / (double)fmaxf(mbg, 1e-12f)
                    - sfg / (double)fmaxf(mfg, 1e-12f);
        }
        cs[bc] = contrib;
    }
    __syncthreads();
    if (threadIdx.x == 0) {
        double s = 0.0;
        #pragma unroll
        for (int k = 0; k < 24; k++) s += cs[k];
        out[0] = (float)(s / (24.0 * (double)HW));
    }
}

extern "C" void kernel_launch(void* const* d_in, const int* in_sizes, int n_in,
                              void* d_out, int out_size) {
    const float* logits  = (const float*)d_in[0];
    const int*   targets = (const int*)d_in[1];

    dim3 g1(W / JT, BATCH);
    k1_masks<<<g1, H>>>(targets);
    dim3 g2(RG, BATCH);
    k2_fused<<<g2, W>>>(logits);
    k3_final<<<1, 24 * 32>>>((float*)d_out);
}